// round 1
// baseline (speedup 1.0000x reference)
#include <cuda_runtime.h>
#include <cuda_bf16.h>

#define NC   3144   // counties
#define TT   156    // time steps
#define TP   154    // predicted steps (T - p)
#define TPAD 160    // padded t dimension (multiple of 32)
#define NNZ  31440
#define CAP  128    // bucket capacity per column (Poisson(10) max ~30)

// -------- scratch (no allocations allowed) --------
__device__ int   g_count[NC];
__device__ int   g_rows[NC * CAP];
__device__ float g_bv[NC * CAP];
__device__ float g_av[NC * CAP];
__device__ float g_hv[NC * CAP];
__device__ float g_csumT[NC * TPAD];   // [m][t] = C[t][m] + C[t+1][m]
__device__ float g_dsumT[NC * TPAD];
__device__ float g_baseCT[NC * TPAD];  // mobility + covariate base terms
__device__ float g_baseDT[NC * TPAD];

// ============================================================
// Kernel 1: lag sums + base terms, transposed to [m][t] layout.
// grid (99, 5), block (32, 32). Also zeroes bucket counters.
// ============================================================
__global__ void prep_kernel(const float* __restrict__ C, const float* __restrict__ D,
                            const float* __restrict__ M, const float* __restrict__ cov,
                            const float* __restrict__ mu, const float* __restrict__ nu,
                            const float* __restrict__ ups, const float* __restrict__ zeta)
{
    __shared__ float sC[32][33], sD[32][33], sBC[32][33], sBD[32][33];
    const int tx = threadIdx.x, ty = threadIdx.y;
    const int m0 = blockIdx.x * 32, t0 = blockIdx.y * 32;

    // zero the bucket counters (first 4 linear blocks cover 3144)
    int gid = (blockIdx.y * gridDim.x + blockIdx.x) * 1024 + ty * 32 + tx;
    if (gid < NC) g_count[gid] = 0;

    const int m = m0 + tx;        // coalesced reads along m
    const int t = t0 + ty;

    float cs = 0.f, ds = 0.f, bc = 0.f, bd = 0.f;
    if (m < NC && t < TP) {
        cs = C[t * NC + m] + C[(t + 1) * NC + m];
        ds = D[t * NC + m] + D[(t + 1) * NC + m];
        float mc = 0.f, md = 0.f;
#pragma unroll
        for (int k = 0; k < 6; k++) {
            float v0 = M[(k * TT + t)     * NC + m];
            float v1 = M[(k * TT + t + 1) * NC + m];
            mc += mu[k * 2 + 0] * v0 + mu[k * 2 + 1] * v1;
            md += nu[k * 2 + 0] * v0 + nu[k * 2 + 1] * v1;
        }
        float cc = 0.f, cd = 0.f;
#pragma unroll
        for (int j = 0; j < 10; j++) {
            float cv = cov[j * NC + m];
            cc += ups[j] * cv;
            cd += zeta[j] * cv;
        }
        bc = mc + cc;
        bd = md + cd;
    }
    sC[ty][tx] = cs; sD[ty][tx] = ds; sBC[ty][tx] = bc; sBD[ty][tx] = bd;
    __syncthreads();

    // transposed, coalesced writes: this thread now owns (m = m0+ty, t = t0+tx)
    const int mw = m0 + ty, tw = t0 + tx;   // tw < 160 always
    if (mw < NC) {
        g_csumT [mw * TPAD + tw] = sC [tx][ty];
        g_dsumT [mw * TPAD + tw] = sD [tx][ty];
        g_baseCT[mw * TPAD + tw] = sBC[tx][ty];
        g_baseDT[mw * TPAD + tw] = sBD[tx][ty];
    }
}

// ============================================================
// Kernel 2: bucket the nonzeros by destination column (CSC-ish)
// ============================================================
__global__ void scatter_kernel(const float* __restrict__ bnz, const float* __restrict__ anz,
                               const float* __restrict__ hnz, const int* __restrict__ rows,
                               const int* __restrict__ cols)
{
    int k = blockIdx.x * 256 + threadIdx.x;
    if (k >= NNZ) return;
    int c = cols[k];
    int slot = atomicAdd(&g_count[c], 1);
    if (slot < CAP) {
        int idx = c * CAP + slot;
        g_rows[idx] = rows[k];
        g_bv[idx]   = bnz[k];
        g_av[idx]   = anz[k];
        g_hv[idx]   = hnz[k];
    }
}

// ============================================================
// Kernel 3: main SpMM-style gather + coalesced output.
// block (32, 16): warp = one column m, lanes cover t (5 chunks of 32).
// grid: ceil(3144/16) = 197 blocks.
// ============================================================
__global__ void main_kernel(float* __restrict__ out)
{
    __shared__ float tile[TPAD][17];   // padded: stride 17 -> conflict-free
    const int tx = threadIdx.x, ty = threadIdx.y;
    const int m0 = blockIdx.x * 16;
    const int m = m0 + ty;
    const bool valid = (m < NC);

    float accC[5], accD[5];
    int cnt = 0;
    if (valid) cnt = min(g_count[m], CAP);

#pragma unroll
    for (int i = 0; i < 5; i++) {
        int t = tx + 32 * i;
        accC[i] = valid ? g_baseCT[m * TPAD + t] : 0.f;
        accD[i] = valid ? g_baseDT[m * TPAD + t] : 0.f;
    }

    const int base = m * CAP;
    for (int s = 0; s < cnt; s++) {
        // warp-uniform metadata (broadcast loads)
        int   r  = g_rows[base + s];
        float bv = g_bv[base + s];
        float av = g_av[base + s];
        float hv = g_hv[base + s];
        const float* __restrict__ cr = &g_csumT[r * TPAD];
        const float* __restrict__ dr = &g_dsumT[r * TPAD];
#pragma unroll
        for (int i = 0; i < 5; i++) {
            int t = tx + 32 * i;
            float cs = cr[t];          // 128B coalesced
            float dv = dr[t];
            accC[i] += bv * cs;
            accD[i] += hv * cs + av * dv;
        }
    }

    const int tid = ty * 32 + tx;

    // ---- C_hat: transpose through smem for coalesced stores ----
#pragma unroll
    for (int i = 0; i < 5; i++) tile[tx + 32 * i][ty] = accC[i];
    __syncthreads();
#pragma unroll
    for (int j = 0; j < 5; j++) {
        int idx = tid + j * 512;           // < 2560
        int t = idx >> 4, mo = idx & 15;
        if (t < TP && (m0 + mo) < NC)
            out[t * NC + m0 + mo] = tile[t][mo];
    }
    __syncthreads();

    // ---- D_hat ----
#pragma unroll
    for (int i = 0; i < 5; i++) tile[tx + 32 * i][ty] = accD[i];
    __syncthreads();
#pragma unroll
    for (int j = 0; j < 5; j++) {
        int idx = tid + j * 512;
        int t = idx >> 4, mo = idx & 15;
        if (t < TP && (m0 + mo) < NC)
            out[(TP + t) * NC + m0 + mo] = tile[t][mo];
    }
}

// ============================================================
extern "C" void kernel_launch(void* const* d_in, const int* in_sizes, int n_in,
                              void* d_out, int out_size)
{
    const float* C    = (const float*)d_in[0];
    const float* D    = (const float*)d_in[1];
    const float* M    = (const float*)d_in[2];
    const float* cov  = (const float*)d_in[3];
    const float* bnz  = (const float*)d_in[4];
    const float* anz  = (const float*)d_in[5];
    const float* hnz  = (const float*)d_in[6];
    const float* mu   = (const float*)d_in[7];
    const float* nu   = (const float*)d_in[8];
    const float* ups  = (const float*)d_in[9];
    const float* zeta = (const float*)d_in[10];
    const int*   rows = (const int*)d_in[11];
    const int*   cols = (const int*)d_in[12];
    float* out = (float*)d_out;

    dim3 pgrid((NC + 31) / 32, (TPAD + 31) / 32);   // (99, 5)
    prep_kernel<<<pgrid, dim3(32, 32)>>>(C, D, M, cov, mu, nu, ups, zeta);

    scatter_kernel<<<(NNZ + 255) / 256, 256>>>(bnz, anz, hnz, rows, cols);

    main_kernel<<<(NC + 15) / 16, dim3(32, 16)>>>(out);
}

// round 2
// speedup vs baseline: 1.1586x; 1.1586x over previous
#include <cuda_runtime.h>
#include <cuda_bf16.h>

#define NC   3144   // counties
#define TT   156    // time steps
#define TP   154    // predicted steps (T - p)
#define TPAD 160    // padded t dimension
#define NNZ  31440
#define CAP  128    // bucket capacity per column (Poisson(10), max ~35)

#define MT          128                 // counties per prep block
#define NMB         25                  // ceil(NC / MT)
#define TC          8                   // t-steps per prep chunk
#define NTC         (TPAD / TC)         // 20
#define PREP_BLOCKS (NMB * NTC)         // 500
#define SCAT_BLOCKS ((NNZ + 127) / 128) // 246

// -------- scratch (no allocations allowed; zero-initialized at load) --------
__device__ int    g_count[NC];
__device__ int4   g_meta[NC * CAP];     // {row, bv, av, hv} packed
__device__ float2 g_csd [NC * TPAD];    // {C[t]+C[t+1], D[t]+D[t+1]} at [m][t]
__device__ float2 g_base[NC * TPAD];    // {mob_c + ups@cov, mob_d + zeta@cov}

// ============================================================
// Kernel A: prep (lag sums + base terms, [m][t] layout) fused
// with nnz scatter into per-column buckets.
// g_count starts at 0 (zero-init first call; main re-zeroes after use).
// ============================================================
__global__ void prep_scatter_kernel(
    const float* __restrict__ C, const float* __restrict__ D,
    const float* __restrict__ M, const float* __restrict__ cov,
    const float* __restrict__ mu, const float* __restrict__ nu,
    const float* __restrict__ ups, const float* __restrict__ zeta,
    const float* __restrict__ bnz, const float* __restrict__ anz,
    const float* __restrict__ hnz, const int* __restrict__ rows,
    const int* __restrict__ cols)
{
    const int b = blockIdx.x;

    // ---------------- scatter blocks ----------------
    if (b >= PREP_BLOCKS) {
        int k = (b - PREP_BLOCKS) * 128 + threadIdx.x;
        if (k < NNZ) {
            int c = cols[k];
            int slot = atomicAdd(&g_count[c], 1);
            if (slot < CAP)
                g_meta[c * CAP + slot] = make_int4(
                    rows[k], __float_as_int(bnz[k]),
                    __float_as_int(anz[k]), __float_as_int(hnz[k]));
        }
        return;
    }

    // ---------------- prep blocks ----------------
    const int mblk = b % NMB, tc = b / NMB;
    const int m = mblk * MT + threadIdx.x;
    if (m >= NC) return;
    const int t0 = tc * TC;

    // uniform small params
    float muv[12], nuv[12];
#pragma unroll
    for (int i = 0; i < 12; i++) { muv[i] = mu[i]; nuv[i] = nu[i]; }

    // covariate terms (t-independent)
    float cc = 0.f, cd = 0.f;
#pragma unroll
    for (int j = 0; j < 10; j++) {
        float cv = cov[j * NC + m];
        cc += ups[j]  * cv;
        cd += zeta[j] * cv;
    }

    // rotating "next" values: C/D/M each loaded exactly once per t
    float cn = C[t0 * NC + m];
    float dn = D[t0 * NC + m];
    float mn[6];
#pragma unroll
    for (int k = 0; k < 6; k++) mn[k] = M[(k * TT + t0) * NC + m];

    float cs8[TC], ds8[TC], bc8[TC], bd8[TC];
#pragma unroll
    for (int j = 0; j < TC; j++) {
        int tn = min(t0 + j + 1, TT - 1);   // clamp: t>=154 lanes are never used
        float c0 = cn;  cn = C[tn * NC + m];
        float d0 = dn;  dn = D[tn * NC + m];
        cs8[j] = c0 + cn;
        ds8[j] = d0 + dn;
        float mc = cc, md = cd;
#pragma unroll
        for (int k = 0; k < 6; k++) {
            float v0 = mn[k];
            float v1 = M[(k * TT + tn) * NC + m];
            mn[k] = v1;
            mc += muv[k * 2] * v0 + muv[k * 2 + 1] * v1;
            md += nuv[k * 2] * v0 + nuv[k * 2 + 1] * v1;
        }
        bc8[j] = mc;
        bd8[j] = md;
    }

    // packed float4 stores: {cs[2j], ds[2j], cs[2j+1], ds[2j+1]}
    float4* pc = reinterpret_cast<float4*>(&g_csd [m * TPAD + t0]);
    float4* pb = reinterpret_cast<float4*>(&g_base[m * TPAD + t0]);
#pragma unroll
    for (int j = 0; j < TC / 2; j++) {
        pc[j] = make_float4(cs8[2*j], ds8[2*j], cs8[2*j+1], ds8[2*j+1]);
        pb[j] = make_float4(bc8[2*j], bd8[2*j], bc8[2*j+1], bd8[2*j+1]);
    }
}

// ============================================================
// Kernel B: sparse gather + coalesced output.
// block (32, 8): warp = one column m, lanes cover t (5 chunks of 32).
// grid: 3144/8 = 393 blocks (exact).
// ============================================================
__global__ void main_kernel(float* __restrict__ out)
{
    __shared__ float2 tile[TPAD][9];    // [t][m_local], 2-way conflicts max
    const int tx = threadIdx.x, ty = threadIdx.y;
    const int m0 = blockIdx.x * 8;
    const int m = m0 + ty;

    int cnt = min(g_count[m], CAP);
    if (tx == 0) g_count[m] = 0;        // re-arm for next graph replay

    float accC[5], accD[5];
#pragma unroll
    for (int i = 0; i < 5; i++) {
        float2 bv = g_base[m * TPAD + tx + 32 * i];
        accC[i] = bv.x;
        accD[i] = bv.y;
    }

    const int4* __restrict__ meta = &g_meta[m * CAP];
    for (int s = 0; s < cnt; s++) {
        int4 md = meta[s];              // warp-uniform broadcast
        int   r  = md.x;
        float bv = __int_as_float(md.y);
        float av = __int_as_float(md.z);
        float hv = __int_as_float(md.w);
        const float2* __restrict__ cr = &g_csd[r * TPAD];
#pragma unroll
        for (int i = 0; i < 5; i++) {
            float2 v = cr[tx + 32 * i]; // 256B coalesced per chunk
            accC[i] += bv * v.x;
            accD[i] += hv * v.x + av * v.y;
        }
    }

    // transpose through smem, coalesced stores
#pragma unroll
    for (int i = 0; i < 5; i++)
        tile[tx + 32 * i][ty] = make_float2(accC[i], accD[i]);
    __syncthreads();

    const int tid = ty * 32 + tx;
#pragma unroll
    for (int j = 0; j < 10; j++) {
        int idx = tid + j * 256;        // < 2560
        int t = idx >> 3, mo = idx & 7;
        if (t < TP) {
            float2 v = tile[t][mo];
            out[t        * NC + m0 + mo] = v.x;
            out[(TP + t) * NC + m0 + mo] = v.y;
        }
    }
}

// ============================================================
extern "C" void kernel_launch(void* const* d_in, const int* in_sizes, int n_in,
                              void* d_out, int out_size)
{
    const float* C    = (const float*)d_in[0];
    const float* D    = (const float*)d_in[1];
    const float* M    = (const float*)d_in[2];
    const float* cov  = (const float*)d_in[3];
    const float* bnz  = (const float*)d_in[4];
    const float* anz  = (const float*)d_in[5];
    const float* hnz  = (const float*)d_in[6];
    const float* mu   = (const float*)d_in[7];
    const float* nu   = (const float*)d_in[8];
    const float* ups  = (const float*)d_in[9];
    const float* zeta = (const float*)d_in[10];
    const int*   rows = (const int*)d_in[11];
    const int*   cols = (const int*)d_in[12];
    float* out = (float*)d_out;

    prep_scatter_kernel<<<PREP_BLOCKS + SCAT_BLOCKS, 128>>>(
        C, D, M, cov, mu, nu, ups, zeta, bnz, anz, hnz, rows, cols);

    main_kernel<<<NC / 8, dim3(32, 8)>>>(out);
}